// round 8
// baseline (speedup 1.0000x reference)
#include <cuda_runtime.h>
#include <cuda_bf16.h>
#include <cstdint>

#define EPSF 1e-5f

constexpr int MROWS = 16384;
constexpr int KDIM  = 1024;
constexpr int NDIM  = 1024;

// GEMM tiling: CTA = 128(M) x 128(N), 8 warps (2M x 4N), warp tile 64x32.
// K-chunk = 64 int8 bytes (16 chunks), 4-stage cp.async pipeline.
// Packed smem: two 64B logical rows per 128B smem row, 8-way XOR swizzle.
constexpr int KT2         = KDIM / 64;         // 16
constexpr int STAGES      = 4;
constexpr int A_TILE      = 128 * 64;          // 8KB
constexpr int STAGE_BYTES = 2 * A_TILE;        // 16KB (A + B)
constexpr int SMEM_TOTAL  = STAGES * STAGE_BYTES; // 64KB -> 3 CTAs/SM

// ---------------- device scratch (no allocations allowed) ----------------
__device__ char  g_qx[(size_t)MROWS * KDIM];  // 16MB int8, row-major [m][k]
__device__ char  g_qw[(size_t)NDIM  * KDIM];  // 1MB  int8, row-major [n][k]
__device__ float g_row_dq[MROWS];             // max|x_row| / 127
__device__ float g_partial[1024];             // per-weight-row |.| sums
__device__ float g_w_factor;                  // clip(mean|w|, eps)

// ---------------- PTX helpers (baseline ISA only; no sm_100a features) ----
__device__ __forceinline__ uint32_t smem_u32(const void* p) {
    uint32_t a;
    asm("{ .reg .u64 t; cvta.to.shared.u64 t, %1; cvt.u32.u64 %0, t; }" : "=r"(a) : "l"(p));
    return a;
}
__device__ __forceinline__ void cp16(uint32_t dst, const void* src) {
    asm volatile("cp.async.cg.shared.global [%0], [%1], 16;" :: "r"(dst), "l"(src));
}
__device__ __forceinline__ void cp_commit() {
    asm volatile("cp.async.commit_group;" ::: "memory");
}
__device__ __forceinline__ void cp_wait2() {
    asm volatile("cp.async.wait_group 2;" ::: "memory");
}
__device__ __forceinline__ void cp_wait1() {
    asm volatile("cp.async.wait_group 1;" ::: "memory");
}
__device__ __forceinline__ void cp_wait0() {
    asm volatile("cp.async.wait_group 0;" ::: "memory");
}
__device__ __forceinline__ void ldm_x4(uint32_t* r, uint32_t addr) {
    asm volatile("ldmatrix.sync.aligned.m8n8.x4.shared.b16 {%0,%1,%2,%3}, [%4];"
                 : "=r"(r[0]), "=r"(r[1]), "=r"(r[2]), "=r"(r[3]) : "r"(addr));
}
__device__ __forceinline__ void mma_s8(int* d, const uint32_t* a, uint32_t b0, uint32_t b1) {
    asm volatile(
        "mma.sync.aligned.m16n8k32.row.col.s32.s8.s8.s32 "
        "{%0,%1,%2,%3}, {%4,%5,%6,%7}, {%8,%9}, {%0,%1,%2,%3};"
        : "+r"(d[0]), "+r"(d[1]), "+r"(d[2]), "+r"(d[3])
        : "r"(a[0]), "r"(a[1]), "r"(a[2]), "r"(a[3]), "r"(b0), "r"(b1));
}

// =========================================================================
// wabs: warp-per-row |w| sums -> g_partial[1024]
// =========================================================================
__global__ void wabs_kernel(const float* __restrict__ w) {
    int wid = threadIdx.x >> 5, lane = threadIdx.x & 31;
    int row = blockIdx.x * 8 + wid;
    const float4* wr = reinterpret_cast<const float4*>(w + (size_t)row * 1024);
    float s = 0.f;
    #pragma unroll
    for (int i = 0; i < 8; i++) {
        float4 v = wr[lane + 32 * i];
        s += fabsf(v.x) + fabsf(v.y) + fabsf(v.z) + fabsf(v.w);
    }
    #pragma unroll
    for (int o = 16; o; o >>= 1) s += __shfl_xor_sync(0xffffffffu, s, o);
    if (lane == 0) g_partial[row] = s;
}

// =========================================================================
// xquant: warp-per-row int8 quantization (no block reduce)
// =========================================================================
__global__ void xquant_kernel(const float* __restrict__ x) {
    int wid = threadIdx.x >> 5, lane = threadIdx.x & 31;
    int row = blockIdx.x * 8 + wid;
    const float4* xr = reinterpret_cast<const float4*>(x + (size_t)row * 1024);
    float4 v[8];
    float mx = 0.f;
    #pragma unroll
    for (int i = 0; i < 8; i++) {
        v[i] = xr[lane + 32 * i];
        mx = fmaxf(mx, fmaxf(fmaxf(fabsf(v[i].x), fabsf(v[i].y)),
                             fmaxf(fabsf(v[i].z), fabsf(v[i].w))));
    }
    #pragma unroll
    for (int o = 16; o; o >>= 1) mx = fmaxf(mx, __shfl_xor_sync(0xffffffffu, mx, o));
    mx = fmaxf(mx, EPSF);
    if (lane == 0) g_row_dq[row] = mx * (1.f / 127.f);
    float scale = 127.f / mx;
    char4* qr = reinterpret_cast<char4*>(g_qx + (size_t)row * 1024);
    #pragma unroll
    for (int i = 0; i < 8; i++) {
        char4 c;
        c.x = (char)__float2int_rn(v[i].x * scale);
        c.y = (char)__float2int_rn(v[i].y * scale);
        c.z = (char)__float2int_rn(v[i].z * scale);
        c.w = (char)__float2int_rn(v[i].w * scale);
        qr[lane + 32 * i] = c;
    }
}

// =========================================================================
// wquant: reduce g_partial -> w_factor, ternary-quantize one weight row
// =========================================================================
__global__ void wquant_kernel(const float* __restrict__ w) {
    __shared__ float red[8];
    __shared__ float s_wf;
    int t = threadIdx.x, n = blockIdx.x;
    float s = g_partial[t] + g_partial[t + 256] + g_partial[t + 512] + g_partial[t + 768];
    #pragma unroll
    for (int o = 16; o; o >>= 1) s += __shfl_xor_sync(0xffffffffu, s, o);
    if ((t & 31) == 0) red[t >> 5] = s;
    __syncthreads();
    if (t == 0) {
        float tot = 0.f;
        #pragma unroll
        for (int i = 0; i < 8; i++) tot += red[i];
        float wf = fmaxf(tot * (1.f / (float)(NDIM * KDIM)), EPSF); // = 1 / w_scale
        s_wf = wf;
        if (n == 0) g_w_factor = wf;
    }
    __syncthreads();
    float inv = 1.f / s_wf; // w_scale
    float4 v = reinterpret_cast<const float4*>(w + (size_t)n * 1024)[t];
    char4 c;
    c.x = (char)(int)fminf(fmaxf(rintf(v.x * inv), -1.f), 1.f);
    c.y = (char)(int)fminf(fmaxf(rintf(v.y * inv), -1.f), 1.f);
    c.z = (char)(int)fminf(fmaxf(rintf(v.z * inv), -1.f), 1.f);
    c.w = (char)(int)fminf(fmaxf(rintf(v.w * inv), -1.f), 1.f);
    *reinterpret_cast<char4*>(g_qw + (size_t)n * 1024 + 4 * t) = c;
}

// =========================================================================
// IMMA GEMM: CTA 128x128, 8 warps (2M x 4N), warp tile 64x32,
// 64B K-chunks, 4-stage cp.async pipeline (3 iters of cover),
// packed 2-rows-per-128B smem layout with 8-way XOR swizzle.
// __launch_bounds__(256, 3): <=84 regs, 64KB smem -> 3 CTAs (24 warps)/SM.
// =========================================================================
__global__ void __launch_bounds__(256, 3)
gemm_kernel(const float* __restrict__ bias, float* __restrict__ out) {
    extern __shared__ __align__(128) char smem[];
    const uint32_t sb = smem_u32(smem);
    const int tid = threadIdx.x;
    const int wid = tid >> 5, lid = tid & 31;
    const int nt = blockIdx.x;   // 0..7
    const int mt = blockIdx.y;   // 0..127
    const int mh = wid >> 2;     // warp M half (0/1)
    const int nq = wid & 3;      // warp N quarter (0..3)

    const char* Aptr = g_qx + (size_t)mt * 128 * KDIM;
    const char* Bptr = g_qw + (size_t)nt * 128 * KDIM;

    // pack: logical row m (0..127), 16B chunk c (0..3) ->
    //   (m>>1)*128 + ((((m&1)*4 + c) ^ ((m>>1)&7)) << 4)
    auto issue = [&](int kt) {
        int s = kt & (STAGES - 1);
        uint32_t base = sb + s * STAGE_BYTES;
        const char* gA = Aptr + kt * 64;
        const char* gB = Bptr + kt * 64;
        #pragma unroll
        for (int r = 0; r < 2; r++) {
            int idx = tid + 256 * r;          // 0..511
            int m = idx >> 2, c = idx & 3;
            uint32_t off = (uint32_t)(((m >> 1) << 7) +
                           (((((m & 1) << 2) + c) ^ ((m >> 1) & 7)) << 4));
            cp16(base + off,          gA + (size_t)m * KDIM + c * 16);
            cp16(base + A_TILE + off, gB + (size_t)m * KDIM + c * 16);
        }
        cp_commit();
    };

    int acc[4][4][4];
    #pragma unroll
    for (int i = 0; i < 4; i++)
        #pragma unroll
        for (int j = 0; j < 4; j++)
            #pragma unroll
            for (int r = 0; r < 4; r++) acc[i][j][r] = 0;

    issue(0);
    issue(1);
    issue(2);

    // per-lane fragment addressing (identical fragment layout to verified R5)
    const int tile   = lid >> 3;               // 0..3 within ldmatrix x4
    const int trow   = lid & 7;
    const int kc     = tile >> 1;              // 16B chunk within 32B k-step
    const int arow   = 64 * mh + ((tile & 1) << 3) + trow;
    const int nrow   = 32 * nq + ((tile & 1) << 3) + trow;
    const int rA = arow >> 1, hA4 = (arow & 1) << 2, keyA = rA & 7;
    const int rB = nrow >> 1, hB4 = (nrow & 1) << 2, keyB = rB & 7;

    for (int kt = 0; kt < KT2; kt++) {
        int rem = KT2 - 1 - kt;
        if (rem >= 2) cp_wait2(); else if (rem == 1) cp_wait1(); else cp_wait0();
        __syncthreads();
        if (kt + STAGES - 1 < KT2) issue(kt + STAGES - 1);

        uint32_t Ab = sb + (kt & (STAGES - 1)) * STAGE_BYTES;
        uint32_t Bb = Ab + A_TILE;

        #pragma unroll
        for (int ks = 0; ks < 2; ks++) {
            int c = ks * 2 + kc;               // 16B chunk 0..3
            uint32_t b[2][4];
            #pragma unroll
            for (int j = 0; j < 2; j++)
                ldm_x4(b[j], Bb + ((rB + 8 * j) << 7) + (((hB4 + c) ^ keyB) << 4));
            #pragma unroll
            for (int i = 0; i < 4; i++) {
                uint32_t a[4];
                ldm_x4(a, Ab + ((rA + 8 * i) << 7) + (((hA4 + c) ^ keyA) << 4));
                #pragma unroll
                for (int jb = 0; jb < 4; jb++)
                    mma_s8(acc[i][jb], a, b[jb >> 1][jb & 1], b[jb >> 1][2 + (jb & 1)]);
            }
        }
    }

    // ---------------- epilogue: dequant + bias, float2 stores ----------------
    const float wf = g_w_factor;
    #pragma unroll
    for (int i = 0; i < 4; i++) {
        int r0 = mt * 128 + 64 * mh + 16 * i + (lid >> 2);
        float rf0 = g_row_dq[r0] * wf;
        float rf1 = g_row_dq[r0 + 8] * wf;
        float* o0 = out + (size_t)r0 * NDIM;
        float* o1 = out + (size_t)(r0 + 8) * NDIM;
        #pragma unroll
        for (int jb = 0; jb < 4; jb++) {
            int col = nt * 128 + 32 * nq + 8 * jb + ((lid & 3) << 1);
            float2 bz = *reinterpret_cast<const float2*>(&bias[col]);
            float2 v0, v1;
            v0.x = (float)acc[i][jb][0] * rf0 + bz.x;
            v0.y = (float)acc[i][jb][1] * rf0 + bz.y;
            v1.x = (float)acc[i][jb][2] * rf1 + bz.x;
            v1.y = (float)acc[i][jb][3] * rf1 + bz.y;
            *reinterpret_cast<float2*>(&o0[col]) = v0;
            *reinterpret_cast<float2*>(&o1[col]) = v1;
        }
    }
}

// =========================================================================
extern "C" void kernel_launch(void* const* d_in, const int* in_sizes, int n_in,
                              void* d_out, int out_size) {
    const float* x    = (const float*)d_in[0];
    const float* w    = (const float*)d_in[1];
    const float* bias = (const float*)d_in[2];
    float* out        = (float*)d_out;

    wabs_kernel<<<128, 256>>>(w);              // idx 0
    xquant_kernel<<<MROWS / 8, 256>>>(x);      // idx 1
    wquant_kernel<<<1024, 256>>>(w);           // idx 2
    cudaFuncSetAttribute(gemm_kernel, cudaFuncAttributeMaxDynamicSharedMemorySize, SMEM_TOTAL);
    gemm_kernel<<<dim3(NDIM / 128, MROWS / 128), 256, SMEM_TOTAL>>>(bias, out); // idx 3
}

// round 9
// speedup vs baseline: 1.0343x; 1.0343x over previous
#include <cuda_runtime.h>
#include <cuda_bf16.h>
#include <cstdint>

#define EPSF 1e-5f

constexpr int MROWS = 16384;
constexpr int KDIM  = 1024;
constexpr int NDIM  = 1024;

// GEMM tiling: CTA = 128(M) x 128(N), 8 warps (2M x 4N), warp tile 64x32,
// K-chunk = 128 int8 bytes, 8 chunks, 3-stage cp.async pipeline.
constexpr int KT          = KDIM / 128;        // 8
constexpr int STAGES      = 3;
constexpr int A_TILE      = 128 * 128;         // 16KB
constexpr int B_TILE      = 128 * 128;         // 16KB
constexpr int STAGE_BYTES = A_TILE + B_TILE;   // 32KB
constexpr int SMEM_TOTAL  = STAGES * STAGE_BYTES; // 96KB -> 2 CTAs/SM

// ---------------- device scratch (no allocations allowed) ----------------
__device__ char  g_qx[(size_t)MROWS * KDIM];  // 16MB int8, row-major [m][k]
__device__ char  g_qw[(size_t)NDIM  * KDIM];  // 1MB  int8, row-major [n][k]
__device__ float g_row_dq[MROWS];             // max|x_row| / 127
__device__ float g_partial[1024];             // per-weight-row |.| sums
__device__ float g_w_factor;                  // clip(mean|w|, eps)
__device__ int   g_flag[128];                 // per-mt "qx tile ready" flags

// ---------------- PTX helpers (baseline ISA only; no sm_100a features) ----
__device__ __forceinline__ uint32_t smem_u32(const void* p) {
    uint32_t a;
    asm("{ .reg .u64 t; cvta.to.shared.u64 t, %1; cvt.u32.u64 %0, t; }" : "=r"(a) : "l"(p));
    return a;
}
__device__ __forceinline__ void cp16(uint32_t dst, const void* src) {
    asm volatile("cp.async.cg.shared.global [%0], [%1], 16;" :: "r"(dst), "l"(src));
}
__device__ __forceinline__ void cp_commit() {
    asm volatile("cp.async.commit_group;" ::: "memory");
}
__device__ __forceinline__ void cp_wait1() {
    asm volatile("cp.async.wait_group 1;" ::: "memory");
}
__device__ __forceinline__ void cp_wait0() {
    asm volatile("cp.async.wait_group 0;" ::: "memory");
}
__device__ __forceinline__ void ldm_x4(uint32_t* r, uint32_t addr) {
    asm volatile("ldmatrix.sync.aligned.m8n8.x4.shared.b16 {%0,%1,%2,%3}, [%4];"
                 : "=r"(r[0]), "=r"(r[1]), "=r"(r[2]), "=r"(r[3]) : "r"(addr));
}
__device__ __forceinline__ void mma_s8(int* d, const uint32_t* a, uint32_t b0, uint32_t b1) {
    asm volatile(
        "mma.sync.aligned.m16n8k32.row.col.s32.s8.s8.s32 "
        "{%0,%1,%2,%3}, {%4,%5,%6,%7}, {%8,%9}, {%0,%1,%2,%3};"
        : "+r"(d[0]), "+r"(d[1]), "+r"(d[2]), "+r"(d[3])
        : "r"(a[0]), "r"(a[1]), "r"(a[2]), "r"(a[3]), "r"(b0), "r"(b1));
}

// =========================================================================
// wabs: warp-per-row |w| sums -> g_partial[1024]; also resets g_flag
// =========================================================================
__global__ void wabs_kernel(const float* __restrict__ w) {
    if (threadIdx.x == 0) g_flag[blockIdx.x] = 0;
    int wid = threadIdx.x >> 5, lane = threadIdx.x & 31;
    int row = blockIdx.x * 8 + wid;
    const float4* wr = reinterpret_cast<const float4*>(w + (size_t)row * 1024);
    float s = 0.f;
    #pragma unroll
    for (int i = 0; i < 8; i++) {
        float4 v = wr[lane + 32 * i];
        s += fabsf(v.x) + fabsf(v.y) + fabsf(v.z) + fabsf(v.w);
    }
    #pragma unroll
    for (int o = 16; o; o >>= 1) s += __shfl_xor_sync(0xffffffffu, s, o);
    if (lane == 0) g_partial[row] = s;
}

// =========================================================================
// wquant: reduce g_partial -> w_factor, ternary-quantize one weight row
// =========================================================================
__global__ void wquant_kernel(const float* __restrict__ w) {
    __shared__ float red[8];
    __shared__ float s_wf;
    int t = threadIdx.x, n = blockIdx.x;
    float s = g_partial[t] + g_partial[t + 256] + g_partial[t + 512] + g_partial[t + 768];
    #pragma unroll
    for (int o = 16; o; o >>= 1) s += __shfl_xor_sync(0xffffffffu, s, o);
    if ((t & 31) == 0) red[t >> 5] = s;
    __syncthreads();
    if (t == 0) {
        float tot = 0.f;
        #pragma unroll
        for (int i = 0; i < 8; i++) tot += red[i];
        float wf = fmaxf(tot * (1.f / (float)(NDIM * KDIM)), EPSF); // = 1 / w_scale
        s_wf = wf;
        if (n == 0) g_w_factor = wf;
    }
    __syncthreads();
    float inv = 1.f / s_wf; // w_scale
    float4 v = reinterpret_cast<const float4*>(w + (size_t)n * 1024)[t];
    char4 c;
    c.x = (char)(int)fminf(fmaxf(rintf(v.x * inv), -1.f), 1.f);
    c.y = (char)(int)fminf(fmaxf(rintf(v.y * inv), -1.f), 1.f);
    c.z = (char)(int)fminf(fmaxf(rintf(v.z * inv), -1.f), 1.f);
    c.w = (char)(int)fminf(fmaxf(rintf(v.w * inv), -1.f), 1.f);
    *reinterpret_cast<char4*>(g_qw + (size_t)n * 1024 + 4 * t) = c;
}

// =========================================================================
// Fused GEMM: nt==0 CTA quantizes its 128 rows of x (warp-per-row), sets
// g_flag[mt]; nt>0 CTAs spin on the flag. Then the verified R5 IMMA loop:
// CTA 128x128, 8 warps (2M x 4N), warp tile 64x32, 3-stage cp.async,
// XOR-swizzled smem, fragment software pipeline, single sync per k-iter.
// =========================================================================
__global__ void __launch_bounds__(256, 2)
gemm_kernel(const float* __restrict__ x, const float* __restrict__ bias,
            float* __restrict__ out) {
    extern __shared__ __align__(128) char smem[];
    const uint32_t sb = smem_u32(smem);
    const int tid = threadIdx.x;
    const int wid = tid >> 5, lid = tid & 31;
    const int nt = blockIdx.x;   // 0..7
    const int mt = blockIdx.y;   // 0..127
    const int mh = wid >> 2;     // warp M half (0/1)
    const int nq = wid & 3;      // warp N quarter (0..3)

    // ---------------- activation quant (producer) / flag wait ----------------
    if (nt == 0) {
        #pragma unroll 1
        for (int it = 0; it < 16; it++) {
            int row = mt * 128 + wid * 16 + it;
            const float4* xr = reinterpret_cast<const float4*>(x + (size_t)row * 1024);
            float4 v[8];
            float mx = 0.f;
            #pragma unroll
            for (int i = 0; i < 8; i++) {
                v[i] = xr[lid + 32 * i];
                mx = fmaxf(mx, fmaxf(fmaxf(fabsf(v[i].x), fabsf(v[i].y)),
                                     fmaxf(fabsf(v[i].z), fabsf(v[i].w))));
            }
            #pragma unroll
            for (int o = 16; o; o >>= 1) mx = fmaxf(mx, __shfl_xor_sync(0xffffffffu, mx, o));
            mx = fmaxf(mx, EPSF);
            if (lid == 0) g_row_dq[row] = mx * (1.f / 127.f);
            float scale = 127.f / mx;
            char4* qr = reinterpret_cast<char4*>(g_qx + (size_t)row * 1024);
            #pragma unroll
            for (int i = 0; i < 8; i++) {
                char4 c;
                c.x = (char)__float2int_rn(v[i].x * scale);
                c.y = (char)__float2int_rn(v[i].y * scale);
                c.z = (char)__float2int_rn(v[i].z * scale);
                c.w = (char)__float2int_rn(v[i].w * scale);
                qr[lid + 32 * i] = c;
            }
        }
        __threadfence();
        __syncthreads();
        if (tid == 0) ((volatile int*)g_flag)[mt] = 1;
    } else {
        if (tid == 0) {
            while (((volatile int*)g_flag)[mt] == 0) __nanosleep(100);
            __threadfence();
        }
        __syncthreads();
    }

    // ---------------- verified R5 GEMM mainloop ----------------
    const char* Aptr = g_qx + (size_t)mt * 128 * KDIM;
    const char* Bptr = g_qw + (size_t)nt * 128 * KDIM;

    auto issue = [&](int kt) {
        int s = kt % STAGES;
        uint32_t base = sb + s * STAGE_BYTES;
        const char* gA = Aptr + kt * 128;
        const char* gB = Bptr + kt * 128;
        #pragma unroll
        for (int r = 0; r < 4; r++) {
            int idx = tid + 256 * r;          // 0..1023
            int row = idx >> 3, c = idx & 7;  // row 0..127, 16B chunk 0..7
            uint32_t sw = (uint32_t)(row * 128 + ((c ^ (row & 7)) << 4));
            cp16(base + sw,          gA + (size_t)row * KDIM + c * 16);
            cp16(base + A_TILE + sw, gB + (size_t)row * KDIM + c * 16);
        }
        cp_commit();
    };

    int acc[4][4][4];
    #pragma unroll
    for (int i = 0; i < 4; i++)
        #pragma unroll
        for (int j = 0; j < 4; j++)
            #pragma unroll
            for (int r = 0; r < 4; r++) acc[i][j][r] = 0;

    issue(0);
    issue(1);

    const int tile   = lid >> 3;          // 0..3 within ldmatrix x4
    const int trow   = lid & 7;
    const int arow_b = 64 * mh + ((tile & 1) << 3) + trow;
    const int nrow_b = 32 * nq + ((tile & 1) << 3) + trow;
    const int kb_hi  = (tile >> 1) << 4;  // 0 or 16 bytes

    for (int kt = 0; kt < KT; kt++) {
        if (kt >= KT - (STAGES - 1)) cp_wait0(); else cp_wait1();
        __syncthreads();                       // single barrier per k-iter
        if (kt + STAGES - 1 < KT) issue(kt + STAGES - 1);

        uint32_t Ab = sb + (kt % STAGES) * STAGE_BYTES;
        uint32_t Bb = Ab + A_TILE;

        uint32_t bfrag[2][2][4];   // [parity][j][4]
        uint32_t abuf[2][4];       // [parity][4]

        auto ldA = [&](uint32_t* dst, int i, int ks) {
            int ar = arow_b + 16 * i;
            int kb = ks * 32 + kb_hi;
            ldm_x4(dst, Ab + ar * 128 + ((((kb >> 4) ^ (ar & 7)) << 4)));
        };
        auto ldB = [&](uint32_t (*dst)[4], int ks) {
            int kb = ks * 32 + kb_hi;
            #pragma unroll
            for (int j = 0; j < 2; j++) {
                int nr = nrow_b + 16 * j;
                ldm_x4(dst[j], Bb + nr * 128 + ((((kb >> 4) ^ (nr & 7)) << 4)));
            }
        };

        ldB(bfrag[0], 0);
        ldA(abuf[0], 0, 0);

        #pragma unroll
        for (int ks = 0; ks < 4; ks++) {
            if (ks < 3) ldB(bfrag[(ks + 1) & 1], ks + 1);
            #pragma unroll
            for (int i = 0; i < 4; i++) {
                int p = (ks * 4 + i) & 1;
                if (i < 3)            ldA(abuf[p ^ 1], i + 1, ks);
                else if (ks < 3)      ldA(abuf[p ^ 1], 0, ks + 1);
                const uint32_t* bk = &bfrag[ks & 1][0][0];
                #pragma unroll
                for (int jb = 0; jb < 4; jb++)
                    mma_s8(acc[i][jb], abuf[p],
                           bk[(jb >> 1) * 4 + (jb & 1)],
                           bk[(jb >> 1) * 4 + 2 + (jb & 1)]);
            }
        }
    }

    // ---------------- epilogue: dequant + bias, float2 stores ----------------
    const float wf = g_w_factor;
    #pragma unroll
    for (int i = 0; i < 4; i++) {
        int r0 = mt * 128 + 64 * mh + 16 * i + (lid >> 2);
        float rf0 = g_row_dq[r0] * wf;
        float rf1 = g_row_dq[r0 + 8] * wf;
        float* o0 = out + (size_t)r0 * NDIM;
        float* o1 = out + (size_t)(r0 + 8) * NDIM;
        #pragma unroll
        for (int jb = 0; jb < 4; jb++) {
            int col = nt * 128 + 32 * nq + 8 * jb + ((lid & 3) << 1);
            float2 bz = *reinterpret_cast<const float2*>(&bias[col]);
            float2 v0, v1;
            v0.x = (float)acc[i][jb][0] * rf0 + bz.x;
            v0.y = (float)acc[i][jb][1] * rf0 + bz.y;
            v1.x = (float)acc[i][jb][2] * rf1 + bz.x;
            v1.y = (float)acc[i][jb][3] * rf1 + bz.y;
            *reinterpret_cast<float2*>(&o0[col]) = v0;
            *reinterpret_cast<float2*>(&o1[col]) = v1;
        }
    }
}

// =========================================================================
extern "C" void kernel_launch(void* const* d_in, const int* in_sizes, int n_in,
                              void* d_out, int out_size) {
    const float* x    = (const float*)d_in[0];
    const float* w    = (const float*)d_in[1];
    const float* bias = (const float*)d_in[2];
    float* out        = (float*)d_out;

    wabs_kernel<<<128, 256>>>(w);              // idx 0 (also resets flags)
    wquant_kernel<<<1024, 256>>>(w);           // idx 1
    cudaFuncSetAttribute(gemm_kernel, cudaFuncAttributeMaxDynamicSharedMemorySize, SMEM_TOTAL);
    gemm_kernel<<<dim3(NDIM / 128, MROWS / 128), 256, SMEM_TOTAL>>>(x, bias, out); // idx 2
}

// round 10
// speedup vs baseline: 1.7511x; 1.6930x over previous
#include <cuda_runtime.h>
#include <cuda_bf16.h>
#include <cstdint>

#define EPSF 1e-5f

constexpr int MROWS = 16384;
constexpr int KDIM  = 1024;
constexpr int NDIM  = 1024;

// GEMM tiling: CTA = 128(M) x 128(N), 8 warps (2M x 4N), warp tile 64x32,
// K-chunk = 128 int8 bytes, 8 chunks, 3-stage cp.async pipeline.
constexpr int KT          = KDIM / 128;        // 8
constexpr int STAGES      = 3;
constexpr int A_TILE      = 128 * 128;         // 16KB
constexpr int B_TILE      = 128 * 128;         // 16KB
constexpr int STAGE_BYTES = A_TILE + B_TILE;   // 32KB
constexpr int SMEM_TOTAL  = STAGES * STAGE_BYTES; // 96KB -> 2 CTAs/SM

// ---------------- device scratch (no allocations allowed) ----------------
__device__ char  g_qx[(size_t)MROWS * KDIM];  // 16MB int8, row-major [m][k]
__device__ char  g_qw[(size_t)NDIM  * KDIM];  // 1MB  int8, row-major [n][k]
__device__ float g_row_dq[MROWS];             // max|x_row| / 127
__device__ float g_partial[1024];             // per-weight-row |.| sums
__device__ float g_w_factor;                  // clip(mean|w|, eps)

// ---------------- PTX helpers (baseline ISA only; no sm_100a features) ----
__device__ __forceinline__ uint32_t smem_u32(const void* p) {
    uint32_t a;
    asm("{ .reg .u64 t; cvta.to.shared.u64 t, %1; cvt.u32.u64 %0, t; }" : "=r"(a) : "l"(p));
    return a;
}
__device__ __forceinline__ void cp16(uint32_t dst, const void* src) {
    asm volatile("cp.async.cg.shared.global [%0], [%1], 16;" :: "r"(dst), "l"(src));
}
__device__ __forceinline__ void cp_commit() {
    asm volatile("cp.async.commit_group;" ::: "memory");
}
__device__ __forceinline__ void cp_wait1() {
    asm volatile("cp.async.wait_group 1;" ::: "memory");
}
__device__ __forceinline__ void cp_wait0() {
    asm volatile("cp.async.wait_group 0;" ::: "memory");
}
__device__ __forceinline__ void ldm_x4(uint32_t* r, uint32_t addr) {
    asm volatile("ldmatrix.sync.aligned.m8n8.x4.shared.b16 {%0,%1,%2,%3}, [%4];"
                 : "=r"(r[0]), "=r"(r[1]), "=r"(r[2]), "=r"(r[3]) : "r"(addr));
}
__device__ __forceinline__ void mma_s8(int* d, const uint32_t* a, uint32_t b0, uint32_t b1) {
    asm volatile(
        "mma.sync.aligned.m16n8k32.row.col.s32.s8.s8.s32 "
        "{%0,%1,%2,%3}, {%4,%5,%6,%7}, {%8,%9}, {%0,%1,%2,%3};"
        : "+r"(d[0]), "+r"(d[1]), "+r"(d[2]), "+r"(d[3])
        : "r"(a[0]), "r"(a[1]), "r"(a[2]), "r"(a[3]), "r"(b0), "r"(b1));
}

// =========================================================================
// Fused quant kernel: blocks [0, 2048) do xquant (8 rows each, warp-per-row);
// blocks [2048, 2176) do wabs (8 weight rows each). Independent tasks, one
// launch -> wabs's 4MB read overlaps xquant's 80MB stream.
// =========================================================================
__global__ void __launch_bounds__(256)
quant_kernel(const float* __restrict__ x, const float* __restrict__ w) {
    int wid = threadIdx.x >> 5, lane = threadIdx.x & 31;
    if (blockIdx.x < MROWS / 8) {
        // ---------------- xquant: warp-per-row int8 quantization ----------
        int row = blockIdx.x * 8 + wid;
        const float4* xr = reinterpret_cast<const float4*>(x + (size_t)row * 1024);
        float4 v[8];
        float mx = 0.f;
        #pragma unroll
        for (int i = 0; i < 8; i++) {
            v[i] = xr[lane + 32 * i];
            mx = fmaxf(mx, fmaxf(fmaxf(fabsf(v[i].x), fabsf(v[i].y)),
                                 fmaxf(fabsf(v[i].z), fabsf(v[i].w))));
        }
        #pragma unroll
        for (int o = 16; o; o >>= 1) mx = fmaxf(mx, __shfl_xor_sync(0xffffffffu, mx, o));
        mx = fmaxf(mx, EPSF);
        if (lane == 0) g_row_dq[row] = mx * (1.f / 127.f);
        float scale = 127.f / mx;
        char4* qr = reinterpret_cast<char4*>(g_qx + (size_t)row * 1024);
        #pragma unroll
        for (int i = 0; i < 8; i++) {
            char4 c;
            c.x = (char)__float2int_rn(v[i].x * scale);
            c.y = (char)__float2int_rn(v[i].y * scale);
            c.z = (char)__float2int_rn(v[i].z * scale);
            c.w = (char)__float2int_rn(v[i].w * scale);
            qr[lane + 32 * i] = c;
        }
    } else {
        // ---------------- wabs: warp-per-row |w| sums ----------------------
        int row = (blockIdx.x - MROWS / 8) * 8 + wid;
        const float4* wr = reinterpret_cast<const float4*>(w + (size_t)row * 1024);
        float s = 0.f;
        #pragma unroll
        for (int i = 0; i < 8; i++) {
            float4 v = wr[lane + 32 * i];
            s += fabsf(v.x) + fabsf(v.y) + fabsf(v.z) + fabsf(v.w);
        }
        #pragma unroll
        for (int o = 16; o; o >>= 1) s += __shfl_xor_sync(0xffffffffu, s, o);
        if (lane == 0) g_partial[row] = s;
    }
}

// =========================================================================
// wquant: reduce g_partial -> w_factor, ternary-quantize one weight row
// =========================================================================
__global__ void wquant_kernel(const float* __restrict__ w) {
    __shared__ float red[8];
    __shared__ float s_wf;
    int t = threadIdx.x, n = blockIdx.x;
    float s = g_partial[t] + g_partial[t + 256] + g_partial[t + 512] + g_partial[t + 768];
    #pragma unroll
    for (int o = 16; o; o >>= 1) s += __shfl_xor_sync(0xffffffffu, s, o);
    if ((t & 31) == 0) red[t >> 5] = s;
    __syncthreads();
    if (t == 0) {
        float tot = 0.f;
        #pragma unroll
        for (int i = 0; i < 8; i++) tot += red[i];
        float wf = fmaxf(tot * (1.f / (float)(NDIM * KDIM)), EPSF); // = 1 / w_scale
        s_wf = wf;
        if (n == 0) g_w_factor = wf;
    }
    __syncthreads();
    float inv = 1.f / s_wf; // w_scale
    float4 v = reinterpret_cast<const float4*>(w + (size_t)n * 1024)[t];
    char4 c;
    c.x = (char)(int)fminf(fmaxf(rintf(v.x * inv), -1.f), 1.f);
    c.y = (char)(int)fminf(fmaxf(rintf(v.y * inv), -1.f), 1.f);
    c.z = (char)(int)fminf(fmaxf(rintf(v.z * inv), -1.f), 1.f);
    c.w = (char)(int)fminf(fmaxf(rintf(v.w * inv), -1.f), 1.f);
    *reinterpret_cast<char4*>(g_qw + (size_t)n * 1024 + 4 * t) = c;
}

// =========================================================================
// IMMA GEMM (verified R5 config): CTA 128x128, 8 warps (2M x 4N), warp tile
// 64x32, mma.m16n8k32.s8, 3-stage cp.async pipeline, XOR-swizzled smem,
// fragment software pipeline, single sync per k-iter, 2 CTAs/SM.
// =========================================================================
__global__ void __launch_bounds__(256, 2)
gemm_kernel(const float* __restrict__ bias, float* __restrict__ out) {
    extern __shared__ __align__(128) char smem[];
    const uint32_t sb = smem_u32(smem);
    const int tid = threadIdx.x;
    const int wid = tid >> 5, lid = tid & 31;
    const int nt = blockIdx.x;   // 0..7
    const int mt = blockIdx.y;   // 0..127
    const int mh = wid >> 2;     // warp M half (0/1)
    const int nq = wid & 3;      // warp N quarter (0..3)

    const char* Aptr = g_qx + (size_t)mt * 128 * KDIM;
    const char* Bptr = g_qw + (size_t)nt * 128 * KDIM;

    auto issue = [&](int kt) {
        int s = kt % STAGES;
        uint32_t base = sb + s * STAGE_BYTES;
        const char* gA = Aptr + kt * 128;
        const char* gB = Bptr + kt * 128;
        #pragma unroll
        for (int r = 0; r < 4; r++) {
            int idx = tid + 256 * r;          // 0..1023
            int row = idx >> 3, c = idx & 7;  // row 0..127, 16B chunk 0..7
            uint32_t sw = (uint32_t)(row * 128 + ((c ^ (row & 7)) << 4));
            cp16(base + sw,          gA + (size_t)row * KDIM + c * 16);
            cp16(base + A_TILE + sw, gB + (size_t)row * KDIM + c * 16);
        }
        cp_commit();
    };

    int acc[4][4][4];
    #pragma unroll
    for (int i = 0; i < 4; i++)
        #pragma unroll
        for (int j = 0; j < 4; j++)
            #pragma unroll
            for (int r = 0; r < 4; r++) acc[i][j][r] = 0;

    issue(0);
    issue(1);

    const int tile   = lid >> 3;          // 0..3 within ldmatrix x4
    const int trow   = lid & 7;
    const int arow_b = 64 * mh + ((tile & 1) << 3) + trow;
    const int nrow_b = 32 * nq + ((tile & 1) << 3) + trow;
    const int kb_hi  = (tile >> 1) << 4;  // 0 or 16 bytes

    for (int kt = 0; kt < KT; kt++) {
        if (kt >= KT - (STAGES - 1)) cp_wait0(); else cp_wait1();
        __syncthreads();                       // single barrier per k-iter
        if (kt + STAGES - 1 < KT) issue(kt + STAGES - 1);

        uint32_t Ab = sb + (kt % STAGES) * STAGE_BYTES;
        uint32_t Bb = Ab + A_TILE;

        uint32_t bfrag[2][2][4];   // [parity][j][4]
        uint32_t abuf[2][4];       // [parity][4]

        auto ldA = [&](uint32_t* dst, int i, int ks) {
            int ar = arow_b + 16 * i;
            int kb = ks * 32 + kb_hi;
            ldm_x4(dst, Ab + ar * 128 + ((((kb >> 4) ^ (ar & 7)) << 4)));
        };
        auto ldB = [&](uint32_t (*dst)[4], int ks) {
            int kb = ks * 32 + kb_hi;
            #pragma unroll
            for (int j = 0; j < 2; j++) {
                int nr = nrow_b + 16 * j;
                ldm_x4(dst[j], Bb + nr * 128 + ((((kb >> 4) ^ (nr & 7)) << 4)));
            }
        };

        ldB(bfrag[0], 0);
        ldA(abuf[0], 0, 0);

        #pragma unroll
        for (int ks = 0; ks < 4; ks++) {
            if (ks < 3) ldB(bfrag[(ks + 1) & 1], ks + 1);
            #pragma unroll
            for (int i = 0; i < 4; i++) {
                int p = (ks * 4 + i) & 1;
                if (i < 3)            ldA(abuf[p ^ 1], i + 1, ks);
                else if (ks < 3)      ldA(abuf[p ^ 1], 0, ks + 1);
                const uint32_t* bk = &bfrag[ks & 1][0][0];
                #pragma unroll
                for (int jb = 0; jb < 4; jb++)
                    mma_s8(acc[i][jb], abuf[p],
                           bk[(jb >> 1) * 4 + (jb & 1)],
                           bk[(jb >> 1) * 4 + 2 + (jb & 1)]);
            }
        }
    }

    // ---------------- epilogue: dequant + bias, float2 stores ----------------
    const float wf = g_w_factor;
    #pragma unroll
    for (int i = 0; i < 4; i++) {
        int r0 = mt * 128 + 64 * mh + 16 * i + (lid >> 2);
        float rf0 = g_row_dq[r0] * wf;
        float rf1 = g_row_dq[r0 + 8] * wf;
        float* o0 = out + (size_t)r0 * NDIM;
        float* o1 = out + (size_t)(r0 + 8) * NDIM;
        #pragma unroll
        for (int jb = 0; jb < 4; jb++) {
            int col = nt * 128 + 32 * nq + 8 * jb + ((lid & 3) << 1);
            float2 bz = *reinterpret_cast<const float2*>(&bias[col]);
            float2 v0, v1;
            v0.x = (float)acc[i][jb][0] * rf0 + bz.x;
            v0.y = (float)acc[i][jb][1] * rf0 + bz.y;
            v1.x = (float)acc[i][jb][2] * rf1 + bz.x;
            v1.y = (float)acc[i][jb][3] * rf1 + bz.y;
            *reinterpret_cast<float2*>(&o0[col]) = v0;
            *reinterpret_cast<float2*>(&o1[col]) = v1;
        }
    }
}

// =========================================================================
extern "C" void kernel_launch(void* const* d_in, const int* in_sizes, int n_in,
                              void* d_out, int out_size) {
    const float* x    = (const float*)d_in[0];
    const float* w    = (const float*)d_in[1];
    const float* bias = (const float*)d_in[2];
    float* out        = (float*)d_out;

    quant_kernel<<<MROWS / 8 + NDIM / 8, 256>>>(x, w);   // idx 0 (xquant ∥ wabs)
    wquant_kernel<<<1024, 256>>>(w);                     // idx 1
    cudaFuncSetAttribute(gemm_kernel, cudaFuncAttributeMaxDynamicSharedMemorySize, SMEM_TOTAL);
    gemm_kernel<<<dim3(NDIM / 128, MROWS / 128), 256, SMEM_TOTAL>>>(bias, out); // idx 2
}